// round 9
// baseline (speedup 1.0000x reference)
#include <cuda_runtime.h>
#include <cuda_fp16.h>
#include <cstdint>

// Problem constants
#define N_U   1024
#define BATCH 4096
#define H     10
#define INV1023 (1.0f / 1023.0f)
#define LOSCALE 2048.0f

// ---------------------------------------------------------------------------
// Scratch (device globals)
// ---------------------------------------------------------------------------
__device__ float g_colpart[32][N_U];
__device__ float g_colsum[N_U];
__device__ float g_rowsum[N_U];
__device__ __align__(16) float g_F[N_U][12];      // padded; cols 10-11 stay 0
__device__ __align__(16) float g_G[N_U][12];      // padded; cols 10-11 stay 0
__device__ __align__(16) float g_ACR[3][12];      // padded

// Split operands (fp16 as ushort). hi = fp16(x); lo = fp16((x-hi)*2048)
__device__ __align__(256) unsigned short g_Ahi[BATCH * N_U];     // 8 MB
__device__ __align__(256) unsigned short g_Alo[BATCH * N_U];     // 8 MB
__device__ __align__(256) unsigned short g_Bhi[N_U * N_U];       // 2 MB  [n][k]
__device__ __align__(256) unsigned short g_Blo[N_U * N_U];       // 2 MB  [n][k]

// ---------------------------------------------------------------------------
// Helpers
// ---------------------------------------------------------------------------
__device__ __forceinline__ uint32_t smem_u32(const void* p) {
    uint32_t a;
    asm("{ .reg .u64 t; cvta.to.shared.u64 t, %1; cvt.u32.u64 %0, t; }" : "=r"(a) : "l"(p));
    return a;
}

#define CP_ASYNC16(dst, src) \
    asm volatile("cp.async.cg.shared.global [%0], [%1], 16;" :: "r"(dst), "l"(src))
#define CP_COMMIT() asm volatile("cp.async.commit_group;")
#define CP_WAIT(n)  asm volatile("cp.async.wait_group %0;" :: "n"(n))

#define LDMATRIX_X4(r0, r1, r2, r3, addr) \
    asm volatile("ldmatrix.sync.aligned.m8n8.x4.shared.b16 {%0,%1,%2,%3}, [%4];" \
        : "=r"(r0), "=r"(r1), "=r"(r2), "=r"(r3) : "r"(addr))

// fp16 inputs, fp32 accumulate
#define MMA_F16F32(c0, c1, c2, c3, a0, a1, a2, a3, b0, b1) \
    asm volatile("mma.sync.aligned.m16n8k16.row.col.f32.f16.f16.f32 " \
        "{%0,%1,%2,%3}, {%4,%5,%6,%7}, {%8,%9}, {%0,%1,%2,%3};" \
        : "+f"(c0), "+f"(c1), "+f"(c2), "+f"(c3) \
        : "r"(a0), "r"(a1), "r"(a2), "r"(a3), "r"(b0), "r"(b1))

// fp16 inputs, fp16 accumulate (2 c-registers, f16x2 each)
#define MMA_F16F16(d0, d1, a0, a1, a2, a3, b0, b1) \
    asm volatile("mma.sync.aligned.m16n8k16.row.col.f16.f16.f16.f16 " \
        "{%0,%1}, {%2,%3,%4,%5}, {%6,%7}, {%0,%1};" \
        : "+r"(d0), "+r"(d1) \
        : "r"(a0), "r"(a1), "r"(a2), "r"(a3), "r"(b0), "r"(b1))

// ---------------------------------------------------------------------------
// Split X -> g_Ahi/g_Alo [m][k]  (fp16 hi, fp16 scaled lo)
// ---------------------------------------------------------------------------
__global__ void __launch_bounds__(256) split_x_kernel(const float* __restrict__ X) {
    int gid = blockIdx.x * 256 + threadIdx.x;
    int idx = gid * 4;
    float4 v = *(const float4*)(X + idx);
    __half hx = __float2half_rn(v.x), hy = __float2half_rn(v.y);
    __half hz = __float2half_rn(v.z), hw = __float2half_rn(v.w);
    __half lx = __float2half_rn((v.x - __half2float(hx)) * LOSCALE);
    __half ly = __float2half_rn((v.y - __half2float(hy)) * LOSCALE);
    __half lz = __float2half_rn((v.z - __half2float(hz)) * LOSCALE);
    __half lw = __float2half_rn((v.w - __half2float(hw)) * LOSCALE);
    uint32_t hi01 = (uint32_t)__half_as_ushort(hx) | ((uint32_t)__half_as_ushort(hy) << 16);
    uint32_t hi23 = (uint32_t)__half_as_ushort(hz) | ((uint32_t)__half_as_ushort(hw) << 16);
    uint32_t lo01 = (uint32_t)__half_as_ushort(lx) | ((uint32_t)__half_as_ushort(ly) << 16);
    uint32_t lo23 = (uint32_t)__half_as_ushort(lz) | ((uint32_t)__half_as_ushort(lw) << 16);
    *(uint2*)(g_Ahi + idx) = make_uint2(hi01, hi23);
    *(uint2*)(g_Alo + idx) = make_uint2(lo01, lo23);
}

// ---------------------------------------------------------------------------
// Fused: column partial sums (blocks 0..127), row sums (128..1151),
// precompute F/G/ACR (1152..1232)
// ---------------------------------------------------------------------------
__global__ void __launch_bounds__(256) fused_sums_kernel(const float* __restrict__ W,
                                                         const float* __restrict__ W1,
                                                         const float* __restrict__ b1) {
    int b = blockIdx.x;
    int tid = threadIdx.x;
    if (b < 128) {
        int rg  = b >> 2;
        int col = (b & 3) * 256 + tid;
        int r0  = rg * 32;
        float s = 0.f;
#pragma unroll
        for (int r = 0; r < 32; r++) s += W[(r0 + r) * N_U + col];
        g_colpart[rg][col] = s;
    } else if (b < 128 + 1024) {
        __shared__ float red[8];
        int row = b - 128;
        float4 v = *(const float4*)(W + row * N_U + tid * 4);
        float s = v.x + v.y + v.z + v.w;
#pragma unroll
        for (int o = 16; o > 0; o >>= 1) s += __shfl_xor_sync(0xffffffffu, s, o);
        if ((tid & 31) == 0) red[tid >> 5] = s;
        __syncthreads();
        if (tid == 0) {
            float t = 0.f;
#pragma unroll
            for (int i = 0; i < 8; i++) t += red[i];
            g_rowsum[row] = t;
        }
    } else {
        int idx = (b - 1152) * 256 + tid;
        if (idx < N_U * H) {
            int i = idx / H, h = idx % H;
            float acc = 0.f;
#pragma unroll
            for (int t = 0; t < 10; t++) {
                float coef = W1[(3 + t) * H + h] + W1[(43 + t) * H + h]
                           - W1[(23 + t) * H + h] * INV1023;
                if ((i >> (9 - t)) & 1) acc += coef;
            }
            g_F[i][h] = acc;
        } else if (idx < 2 * N_U * H) {
            int r = idx - N_U * H;
            int j = r / H, h = r % H;
            float acc = b1[h];
#pragma unroll
            for (int s = 0; s < 10; s++) {
                float coef = W1[(13 + s) * H + h] + W1[(33 + s) * H + h]
                           - W1[(53 + s) * H + h] * INV1023;
                if ((j >> (9 - s)) & 1) acc += coef;
                acc += (512.f * INV1023) * (W1[(23 + s) * H + h] + W1[(53 + s) * H + h]);
            }
            g_G[j][h] = acc;
        } else if (idx < 2 * N_U * H + H) {
            int h = idx - 2 * N_U * H;
            g_ACR[0][h] = W1[h] - (W1[H + h] + W1[2 * H + h]) * INV1023;
            g_ACR[1][h] = W1[H + h] * INV1023;
            g_ACR[2][h] = W1[2 * H + h] * INV1023;
        }
    }
}

__global__ void __launch_bounds__(256) colsum_kernel() {
    int col = blockIdx.x * 256 + threadIdx.x;
    float s = 0.f;
#pragma unroll
    for (int b = 0; b < 32; b++) s += g_colpart[b][col];
    g_colsum[col] = s;
}

// ---------------------------------------------------------------------------
// Fused per-cell MLP + transpose + fp16 split -> g_Bhi/g_Blo directly.
// Grid 1024 blocks: block handles 32x32 tile (i0 = (b>>5)*32, j0 = (b&31)*32).
// Each thread computes 4 cells; tile is transposed through smem.
// ---------------------------------------------------------------------------
__global__ void __launch_bounds__(256) mlp_kernel(const float* __restrict__ W,
                                                  const float* __restrict__ W2,
                                                  const float* __restrict__ b2,
                                                  const float* __restrict__ W3,
                                                  const float* __restrict__ b3) {
    __shared__ __align__(16) float sW2T[H][12];   // [k][h] transposed, padded
    __shared__ __align__(16) float sACR[3][12];
    __shared__ __align__(16) float sF[32][12];
    __shared__ __align__(16) float sG[32][12];
    __shared__ float sRow[32], sCol[32], sB2[H], sW3[H];
    __shared__ float sb3v;
    __shared__ float sNW[32][33];

    int tid = threadIdx.x;
    int i0 = (blockIdx.x >> 5) * 32;
    int j0 = (blockIdx.x & 31) * 32;

    if (tid < 120) {
        int k = tid / 12, h = tid % 12;
        sW2T[k][h] = (h < H) ? W2[h * H + k] : 0.f;
    }
    if (tid >= 128 && tid < 164) {
        int r = tid - 128;
        sACR[r / 12][r % 12] = g_ACR[r / 12][r % 12];
    }
    if (tid >= 192 && tid < 224) {
        int r = tid - 192;
        sRow[r] = g_rowsum[i0 + r];
        sCol[r] = g_colsum[j0 + r];
    }
    for (int s = tid; s < 384; s += 256) {
        int r = s / 12, hh = s % 12;
        sF[r][hh] = g_F[i0 + r][hh];
        sG[r][hh] = g_G[j0 + r][hh];
    }
    if (tid < H) { sB2[tid] = b2[tid]; sW3[tid] = W3[tid * 21]; }
    if (tid == 0) sb3v = b3[0];
    __syncthreads();

    int c  = tid & 31;                 // col within tile
    int r8 = tid >> 5;                 // 0..7
    float csv = sCol[c];
#pragma unroll
    for (int s = 0; s < 4; s++) {
        int r = s * 8 + r8;
        int i = i0 + r, j = j0 + c;
        float w  = W[i * N_U + j];
        float rs = sRow[r];
        float z[12];
        const float4* A4 = (const float4*)sACR[0];
        const float4* C4 = (const float4*)sACR[1];
        const float4* R4 = (const float4*)sACR[2];
        const float4* F4 = (const float4*)sF[r];
        const float4* G4 = (const float4*)sG[c];
#pragma unroll
        for (int q = 0; q < 3; q++) {
            float4 a = A4[q], cc = C4[q], rr = R4[q], f = F4[q], g = G4[q];
            z[q * 4 + 0] = fmaxf(fmaf(a.x, w, fmaf(cc.x, csv, fmaf(rr.x, rs, f.x + g.x))), 0.f);
            z[q * 4 + 1] = fmaxf(fmaf(a.y, w, fmaf(cc.y, csv, fmaf(rr.y, rs, f.y + g.y))), 0.f);
            z[q * 4 + 2] = fmaxf(fmaf(a.z, w, fmaf(cc.z, csv, fmaf(rr.z, rs, f.z + g.z))), 0.f);
            z[q * 4 + 3] = fmaxf(fmaf(a.w, w, fmaf(cc.w, csv, fmaf(rr.w, rs, f.w + g.w))), 0.f);
        }
        float upd = sb3v;
#pragma unroll
        for (int k = 0; k < H; k++) {
            const float4* w4 = (const float4*)sW2T[k];
            float4 wa = w4[0], wb = w4[1];
            float2 wc = *(const float2*)&sW2T[k][8];
            float y = sB2[k];
            y = fmaf(z[0], wa.x, y);
            y = fmaf(z[1], wa.y, y);
            y = fmaf(z[2], wa.z, y);
            y = fmaf(z[3], wa.w, y);
            y = fmaf(z[4], wb.x, y);
            y = fmaf(z[5], wb.y, y);
            y = fmaf(z[6], wb.z, y);
            y = fmaf(z[7], wb.w, y);
            y = fmaf(z[8], wc.x, y);
            y = fmaf(z[9], wc.y, y);
            upd = fmaf(fmaxf(y, 0.f), sW3[k], upd);
        }
        sNW[r][c] = w + upd;
    }
    __syncthreads();

    // Write transposed fp16 split: g_B*[j][i]
    int jj = tid >> 3;                 // 0..31
    int qq = tid & 7;                  // 0..7 (4 i's each)
    uint32_t hiw[2], low[2];
#pragma unroll
    for (int u = 0; u < 4; u++) {
        float v  = sNW[qq * 4 + u][jj];
        __half h = __float2half_rn(v);
        __half l = __float2half_rn((v - __half2float(h)) * LOSCALE);
        ((unsigned short*)hiw)[u] = __half_as_ushort(h);
        ((unsigned short*)low)[u] = __half_as_ushort(l);
    }
    size_t base = (size_t)(j0 + jj) * N_U + i0 + qq * 4;
    *(uint2*)(g_Bhi + base) = make_uint2(hiw[0], hiw[1]);
    *(uint2*)(g_Blo + base) = make_uint2(low[0], low[1]);
}

// ---------------------------------------------------------------------------
// GEMM: out = relu( (Alo*Bhi + Ahi*Blo)/2048  +  Ahi*Bhi )
// Segments 0,1 (iters 0..63):  fp16-accumulate MMA into packed f16x2 regs
// Segment  2 (iters 64..95):   fp32-accumulate on top (after /2048 convert)
// BM=112, BN=256 -> grid 37x4 = 148 CTAs (one balanced wave).
// 256 threads, 8 warps: warp covers 112 rows x 32 cols (7x4 frags).
// ---------------------------------------------------------------------------
#define BM 112
#define BN 256
#define BK 32
#define STAGES 4
#define AROW 40
#define ABYTES (BM * AROW * 2)           // 8960
#define BBYTES (BN * AROW * 2)           // 20480
#define STBYTES (ABYTES + BBYTES)        // 29440
#define SMEM_GEMM (STAGES * STBYTES)     // 117760

__global__ void __launch_bounds__(256, 1) gemm_mma_kernel(float* __restrict__ out) {
    extern __shared__ char smem[];
    uint32_t sb = smem_u32(smem);
    int tid  = threadIdx.x;
    int wid  = tid >> 5;
    int lane = tid & 31;

    int mt = blockIdx.x % 37;
    int nt = blockIdx.x / 37;
    int nw = wid;

    const unsigned short* Aseg[3];
    const unsigned short* Bseg[3];
    Aseg[0] = g_Alo;  Aseg[1] = g_Ahi;  Aseg[2] = g_Ahi;
    Bseg[0] = g_Bhi + (size_t)(nt * BN) * N_U;
    Bseg[1] = g_Blo + (size_t)(nt * BN) * N_U;
    Bseg[2] = Bseg[0];

    union Acc {
        float    f[7][4][4];
        uint32_t u[7][4][2];             // overlays first 56 words
    } acc;
#pragma unroll
    for (int f = 0; f < 7; f++)
#pragma unroll
        for (int n = 0; n < 4; n++)
#pragma unroll
            for (int q = 0; q < 4; q++) acc.f[f][n][q] = 0.f;

    const int ITERS = 96;

    auto load_stage = [&](int it, int st) {
        int seg = it >> 5;
        int k0  = (it & 31) * BK;
        uint32_t abase = sb + st * STBYTES;
        uint32_t bbase = abase + ABYTES;
        const unsigned short* Ag = Aseg[seg];
        const unsigned short* Bg = Bseg[seg];
#pragma unroll
        for (int q = 0; q < 2; q++) {
            int chunk = tid + q * 256;
            if (chunk < BM * 4) {
                int row = chunk >> 2;
                int off = (chunk & 3) * 8;
                int grow = mt * BM + row;
                if (grow > 4095) grow = 4095;
                CP_ASYNC16(abase + row * (AROW * 2) + off * 2,
                           (const char*)(Ag + (size_t)grow * N_U + k0 + off));
            }
        }
#pragma unroll
        for (int q = 0; q < 4; q++) {
            int chunk = tid + q * 256;
            int row = chunk >> 2;
            int off = (chunk & 3) * 8;
            CP_ASYNC16(bbase + row * (AROW * 2) + off * 2,
                       (const char*)(Bg + (size_t)row * N_U + k0 + off));
        }
    };

#pragma unroll
    for (int s = 0; s < STAGES - 1; s++) {
        load_stage(s, s);
        CP_COMMIT();
    }

    int lrow = lane & 15;
    int lcol = (lane >> 4) * 16;

    for (int i = 0; i < ITERS; i++) {
        CP_WAIT(2);
        __syncthreads();

        int nx = i + STAGES - 1;
        if (nx < ITERS) load_stage(nx, nx & (STAGES - 1));
        CP_COMMIT();

        if (i == 64) {
            // Convert packed f16 corrections to f32 (/2048), descending order
            // (dst words [4m,4m+3] never clobber src words [2m',2m'+1], m'<=m)
            const float S = 1.f / LOSCALE;
#pragma unroll
            for (int m = 27; m >= 0; m--) {
                int f = m >> 2, n = m & 3;
                uint32_t u0 = acc.u[f][n][0], u1 = acc.u[f][n][1];
                __half2 h0 = *reinterpret_cast<__half2*>(&u0);
                __half2 h1 = *reinterpret_cast<__half2*>(&u1);
                acc.f[f][n][0] = __low2float(h0) * S;
                acc.f[f][n][1] = __high2float(h0) * S;
                acc.f[f][n][2] = __low2float(h1) * S;
                acc.f[f][n][3] = __high2float(h1) * S;
            }
        }

        int st = i & (STAGES - 1);
        uint32_t abase = sb + st * STBYTES;
        uint32_t bbase = abase + ABYTES;

#pragma unroll
        for (int ks = 0; ks < 2; ks++) {
            uint32_t a[7][4];
#pragma unroll
            for (int f = 0; f < 7; f++)
                LDMATRIX_X4(a[f][0], a[f][1], a[f][2], a[f][3],
                    abase + (f * 16 + lrow) * (AROW * 2) + ks * 32 + lcol);
            uint32_t b[4][2];
#pragma unroll
            for (int g = 0; g < 2; g++) {
                uint32_t r0, r1, r2, r3;
                LDMATRIX_X4(r0, r1, r2, r3,
                    bbase + (nw * 32 + g * 16 + lrow) * (AROW * 2) + ks * 32 + lcol);
                b[2 * g][0] = r0;  b[2 * g][1] = r2;
                b[2 * g + 1][0] = r1;  b[2 * g + 1][1] = r3;
            }
            if (i < 64) {
#pragma unroll
                for (int f = 0; f < 7; f++)
#pragma unroll
                    for (int n = 0; n < 4; n++)
                        MMA_F16F16(acc.u[f][n][0], acc.u[f][n][1],
                                   a[f][0], a[f][1], a[f][2], a[f][3], b[n][0], b[n][1]);
            } else {
#pragma unroll
                for (int f = 0; f < 7; f++)
#pragma unroll
                    for (int n = 0; n < 4; n++)
                        MMA_F16F32(acc.f[f][n][0], acc.f[f][n][1], acc.f[f][n][2], acc.f[f][n][3],
                                   a[f][0], a[f][1], a[f][2], a[f][3], b[n][0], b[n][1]);
            }
        }
    }

    // Epilogue: relu + guarded store
    int cbase = nt * BN + nw * 32 + (lane & 3) * 2;
#pragma unroll
    for (int f = 0; f < 7; f++) {
        int r = mt * BM + f * 16 + (lane >> 2);
#pragma unroll
        for (int n = 0; n < 4; n++) {
            int cc = cbase + n * 8;
            if (r < BATCH) {
                float2 v0;
                v0.x = fmaxf(acc.f[f][n][0], 0.f);
                v0.y = fmaxf(acc.f[f][n][1], 0.f);
                *(float2*)(out + (size_t)r * N_U + cc) = v0;
            }
            if (r + 8 < BATCH) {
                float2 v1;
                v1.x = fmaxf(acc.f[f][n][2], 0.f);
                v1.y = fmaxf(acc.f[f][n][3], 0.f);
                *(float2*)(out + (size_t)(r + 8) * N_U + cc) = v1;
            }
        }
    }
}

// ---------------------------------------------------------------------------
// Row softmax in-place
// ---------------------------------------------------------------------------
__global__ void __launch_bounds__(256) softmax_kernel(float* __restrict__ out) {
    __shared__ float redm[8];
    __shared__ float reds[8];
    __shared__ float bval[2];
    int row = blockIdx.x, tid = threadIdx.x;
    int lane = tid & 31, wid = tid >> 5;

    float4 v = *(float4*)(out + row * N_U + tid * 4);
    float m = fmaxf(fmaxf(v.x, v.y), fmaxf(v.z, v.w));
#pragma unroll
    for (int o = 16; o > 0; o >>= 1) m = fmaxf(m, __shfl_xor_sync(0xffffffffu, m, o));
    if (lane == 0) redm[wid] = m;
    __syncthreads();
    if (tid == 0) {
        float t = redm[0];
#pragma unroll
        for (int i = 1; i < 8; i++) t = fmaxf(t, redm[i]);
        bval[0] = t;
    }
    __syncthreads();
    m = bval[0];
    v.x = __expf(v.x - m); v.y = __expf(v.y - m);
    v.z = __expf(v.z - m); v.w = __expf(v.w - m);
    float s = v.x + v.y + v.z + v.w;
#pragma unroll
    for (int o = 16; o > 0; o >>= 1) s += __shfl_xor_sync(0xffffffffu, s, o);
    if (lane == 0) reds[wid] = s;
    __syncthreads();
    if (tid == 0) {
        float t = 0.f;
#pragma unroll
        for (int i = 0; i < 8; i++) t += reds[i];
        bval[1] = 1.f / t;
    }
    __syncthreads();
    float inv = bval[1];
    v.x *= inv; v.y *= inv; v.z *= inv; v.w *= inv;
    *(float4*)(out + row * N_U + tid * 4) = v;
}

// ---------------------------------------------------------------------------
// Entry point
// ---------------------------------------------------------------------------
extern "C" void kernel_launch(void* const* d_in, const int* in_sizes, int n_in,
                              void* d_out, int out_size) {
    const float* X      = (const float*)d_in[0];
    const float* weight = (const float*)d_in[1];
    const float* W1     = (const float*)d_in[3];
    const float* b1     = (const float*)d_in[4];
    const float* W2     = (const float*)d_in[5];
    const float* b2     = (const float*)d_in[6];
    const float* W3     = (const float*)d_in[7];
    const float* b3     = (const float*)d_in[8];
    float* out = (float*)d_out;

    static bool attr_done = false;
    if (!attr_done) {
        cudaFuncSetAttribute(gemm_mma_kernel,
                             cudaFuncAttributeMaxDynamicSharedMemorySize, SMEM_GEMM);
        attr_done = true;
    }

    split_x_kernel<<<BATCH * N_U / 1024, 256>>>(X);                     // 1
    fused_sums_kernel<<<128 + 1024 + 81, 256>>>(weight, W1, b1);        // 2
    colsum_kernel<<<4, 256>>>();                                        // 3
    mlp_kernel<<<1024, 256>>>(weight, W2, b2, W3, b3);                  // 4
    gemm_mma_kernel<<<148, 256, SMEM_GEMM>>>(out);                      // 5
    softmax_kernel<<<BATCH, 256>>>(out);                                // 6
}

// round 10
// speedup vs baseline: 1.1416x; 1.1416x over previous
#include <cuda_runtime.h>
#include <cuda_fp16.h>
#include <cstdint>

// Problem constants
#define N_U   1024
#define BATCH 4096
#define H     10
#define INV1023 (1.0f / 1023.0f)

// ---------------------------------------------------------------------------
// Scratch (device globals)
// ---------------------------------------------------------------------------
__device__ float g_colpart[32][N_U];
__device__ float g_rowsum[N_U];
__device__ __align__(16) float g_F[N_U][12];      // padded; cols 10-11 stay 0
__device__ __align__(16) float g_G[N_U][12];
__device__ __align__(16) float g_IF[N_U][12];     // R_h*rowsum_i + F[i][h]
__device__ __align__(16) float g_JG[N_U][12];     // C_h*colsum_j + G[j][h] (+b1 inside G)
__device__ __align__(16) float g_ACR[3][12];      // padded; zero-init covers 10,11
__device__ __align__(256) float g_NW[N_U * N_U];  // new_weight [k][n]

// Split operands (fp16 bits in ushort). hi = fp16(x); lo = fp16(x - hi) (unscaled)
__device__ __align__(256) unsigned short g_Ahi[BATCH * N_U];     // 8 MB
__device__ __align__(256) unsigned short g_Alo[BATCH * N_U];     // 8 MB
__device__ __align__(256) unsigned short g_Bhi[N_U * N_U];       // 2 MB  [n][k]
__device__ __align__(256) unsigned short g_Blo[N_U * N_U];       // 2 MB  [n][k]

// ---------------------------------------------------------------------------
// Helpers
// ---------------------------------------------------------------------------
__device__ __forceinline__ uint32_t smem_u32(const void* p) {
    uint32_t a;
    asm("{ .reg .u64 t; cvta.to.shared.u64 t, %1; cvt.u32.u64 %0, t; }" : "=r"(a) : "l"(p));
    return a;
}

#define CP_ASYNC16(dst, src) \
    asm volatile("cp.async.cg.shared.global [%0], [%1], 16;" :: "r"(dst), "l"(src))
#define CP_COMMIT() asm volatile("cp.async.commit_group;")
#define CP_WAIT(n)  asm volatile("cp.async.wait_group %0;" :: "n"(n))

#define LDMATRIX_X4(r0, r1, r2, r3, addr) \
    asm volatile("ldmatrix.sync.aligned.m8n8.x4.shared.b16 {%0,%1,%2,%3}, [%4];" \
        : "=r"(r0), "=r"(r1), "=r"(r2), "=r"(r3) : "r"(addr))

#define MMA_F16F32(c0, c1, c2, c3, a0, a1, a2, a3, b0, b1) \
    asm volatile("mma.sync.aligned.m16n8k16.row.col.f32.f16.f16.f32 " \
        "{%0,%1,%2,%3}, {%4,%5,%6,%7}, {%8,%9}, {%0,%1,%2,%3};" \
        : "+f"(c0), "+f"(c1), "+f"(c2), "+f"(c3) \
        : "r"(a0), "r"(a1), "r"(a2), "r"(a3), "r"(b0), "r"(b1))

// ---------------------------------------------------------------------------
// Kernel 1 (fused, all-independent blocks):
//   b in [0,4096)      : split X -> g_Ahi/g_Alo (fp16 hi/lo)
//   b in [4096,4224)   : column partial sums of W
//   b in [4224,5248)   : row sums of W
//   b in [5248,5329)   : precompute F/G/ACR tables from W1/b1
// ---------------------------------------------------------------------------
__global__ void __launch_bounds__(256) prep_kernel(const float* __restrict__ X,
                                                   const float* __restrict__ W,
                                                   const float* __restrict__ W1,
                                                   const float* __restrict__ b1) {
    __shared__ float red[8];
    int b = blockIdx.x;
    int tid = threadIdx.x;
    if (b < 4096) {
        int gid = b * 256 + tid;
        int idx = gid * 4;
        float4 v = *(const float4*)(X + idx);
        __half hx = __float2half_rn(v.x), hy = __float2half_rn(v.y);
        __half hz = __float2half_rn(v.z), hw = __float2half_rn(v.w);
        __half lx = __float2half_rn(v.x - __half2float(hx));
        __half ly = __float2half_rn(v.y - __half2float(hy));
        __half lz = __float2half_rn(v.z - __half2float(hz));
        __half lw = __float2half_rn(v.w - __half2float(hw));
        uint32_t hi01 = (uint32_t)__half_as_ushort(hx) | ((uint32_t)__half_as_ushort(hy) << 16);
        uint32_t hi23 = (uint32_t)__half_as_ushort(hz) | ((uint32_t)__half_as_ushort(hw) << 16);
        uint32_t lo01 = (uint32_t)__half_as_ushort(lx) | ((uint32_t)__half_as_ushort(ly) << 16);
        uint32_t lo23 = (uint32_t)__half_as_ushort(lz) | ((uint32_t)__half_as_ushort(lw) << 16);
        *(uint2*)(g_Ahi + idx) = make_uint2(hi01, hi23);
        *(uint2*)(g_Alo + idx) = make_uint2(lo01, lo23);
    } else if (b < 4224) {
        int b2 = b - 4096;
        int rg  = b2 >> 2;
        int col = (b2 & 3) * 256 + tid;
        int r0  = rg * 32;
        float s = 0.f;
#pragma unroll
        for (int r = 0; r < 32; r++) s += W[(r0 + r) * N_U + col];
        g_colpart[rg][col] = s;
    } else if (b < 5248) {
        int row = b - 4224;
        float4 v = *(const float4*)(W + row * N_U + tid * 4);
        float s = v.x + v.y + v.z + v.w;
#pragma unroll
        for (int o = 16; o > 0; o >>= 1) s += __shfl_xor_sync(0xffffffffu, s, o);
        if ((tid & 31) == 0) red[tid >> 5] = s;
        __syncthreads();
        if (tid == 0) {
            float t = 0.f;
#pragma unroll
            for (int i = 0; i < 8; i++) t += red[i];
            g_rowsum[row] = t;
        }
    } else {
        int idx = (b - 5248) * 256 + tid;
        if (idx < N_U * H) {
            int i = idx / H, h = idx % H;
            float acc = 0.f;
#pragma unroll
            for (int t = 0; t < 10; t++) {
                float coef = W1[(3 + t) * H + h] + W1[(43 + t) * H + h]
                           - W1[(23 + t) * H + h] * INV1023;
                if ((i >> (9 - t)) & 1) acc += coef;
            }
            g_F[i][h] = acc;
        } else if (idx < 2 * N_U * H) {
            int r = idx - N_U * H;
            int j = r / H, h = r % H;
            float acc = b1[h];
#pragma unroll
            for (int s = 0; s < 10; s++) {
                float coef = W1[(13 + s) * H + h] + W1[(33 + s) * H + h]
                           - W1[(53 + s) * H + h] * INV1023;
                if ((j >> (9 - s)) & 1) acc += coef;
                acc += (512.f * INV1023) * (W1[(23 + s) * H + h] + W1[(53 + s) * H + h]);
            }
            g_G[j][h] = acc;
        } else if (idx < 2 * N_U * H + H) {
            int h = idx - 2 * N_U * H;
            g_ACR[0][h] = W1[h] - (W1[H + h] + W1[2 * H + h]) * INV1023;
            g_ACR[1][h] = W1[H + h] * INV1023;
            g_ACR[2][h] = W1[2 * H + h] * INV1023;
        }
    }
}

// ---------------------------------------------------------------------------
// Kernel 2: finish column sums; build folded tables
//   b in [0,4): JG[j][h] = ACR1[h]*colsum_j + G[j][h]
//   b in [4,8): IF[i][h] = ACR2[h]*rowsum_i + F[i][h]
// ---------------------------------------------------------------------------
__global__ void __launch_bounds__(256) fold_kernel() {
    int b = blockIdx.x;
    int tid = threadIdx.x;
    if (b < 4) {
        int col = b * 256 + tid;
        float s = 0.f;
#pragma unroll
        for (int p = 0; p < 32; p++) s += g_colpart[p][col];
#pragma unroll
        for (int q = 0; q < 3; q++) {
            float4 c = ((const float4*)g_ACR[1])[q];
            float4 g = ((const float4*)g_G[col])[q];
            float4 r;
            r.x = fmaf(c.x, s, g.x);
            r.y = fmaf(c.y, s, g.y);
            r.z = fmaf(c.z, s, g.z);
            r.w = fmaf(c.w, s, g.w);
            ((float4*)g_JG[col])[q] = r;
        }
    } else {
        int i = (b - 4) * 256 + tid;
        float s = g_rowsum[i];
#pragma unroll
        for (int q = 0; q < 3; q++) {
            float4 c = ((const float4*)g_ACR[2])[q];
            float4 f = ((const float4*)g_F[i])[q];
            float4 r;
            r.x = fmaf(c.x, s, f.x);
            r.y = fmaf(c.y, s, f.y);
            r.z = fmaf(c.z, s, f.z);
            r.w = fmaf(c.w, s, f.w);
            ((float4*)g_IF[i])[q] = r;
        }
    }
}

// ---------------------------------------------------------------------------
// Per-cell MLP -> g_NW.  One block per row i; FOUR columns per thread.
// Layer 1: z_h = relu(A_h*w + IF[i][h] + JG[j][h])
// ---------------------------------------------------------------------------
__global__ void __launch_bounds__(256) mlp_kernel(const float* __restrict__ W,
                                                  const float* __restrict__ W2,
                                                  const float* __restrict__ b2,
                                                  const float* __restrict__ W3,
                                                  const float* __restrict__ b3) {
    __shared__ __align__(16) float sW2T[H][12];   // [k][h] transposed, padded
    __shared__ __align__(16) float sA[12];
    __shared__ __align__(16) float sIF[12];
    __shared__ float sB2[H], sW3[H];
    __shared__ float sb3;
    int tid = threadIdx.x;
    int i = blockIdx.x;

    if (tid < 120) {
        int k = tid / 12, h = tid % 12;
        sW2T[k][h] = (h < H) ? W2[h * H + k] : 0.f;
    }
    if (tid >= 128 && tid < 140) sA[tid - 128]  = g_ACR[0][tid - 128];
    if (tid >= 160 && tid < 172) sIF[tid - 160] = g_IF[i][tid - 160];
    if (tid < H) { sB2[tid] = b2[tid]; sW3[tid] = W3[tid * 21]; }
    if (tid == 0) sb3 = b3[0];
    __syncthreads();

    float w[4];
#pragma unroll
    for (int c = 0; c < 4; c++) w[c] = W[i * N_U + c * 256 + tid];

    float z[4][12];
#pragma unroll
    for (int q = 0; q < 3; q++) {
        float4 a = ((const float4*)sA)[q];
        float4 f = ((const float4*)sIF)[q];
#pragma unroll
        for (int c = 0; c < 4; c++) {
            int j = c * 256 + tid;
            float4 g = ((const float4*)g_JG[j])[q];
            float tx = f.x + g.x, ty = f.y + g.y, tz = f.z + g.z, tw = f.w + g.w;
            z[c][q * 4 + 0] = fmaxf(fmaf(a.x, w[c], tx), 0.f);
            z[c][q * 4 + 1] = fmaxf(fmaf(a.y, w[c], ty), 0.f);
            z[c][q * 4 + 2] = fmaxf(fmaf(a.z, w[c], tz), 0.f);
            z[c][q * 4 + 3] = fmaxf(fmaf(a.w, w[c], tw), 0.f);
        }
    }

    float upd[4] = {sb3, sb3, sb3, sb3};
#pragma unroll
    for (int k = 0; k < H; k++) {
        const float4* w4 = (const float4*)sW2T[k];
        float4 wa = w4[0], wb = w4[1];
        float2 wc = *(const float2*)&sW2T[k][8];
        float bk = sB2[k], w3k = sW3[k];
#pragma unroll
        for (int c = 0; c < 4; c++) {
            float y = bk;
            y = fmaf(z[c][0], wa.x, y);
            y = fmaf(z[c][1], wa.y, y);
            y = fmaf(z[c][2], wa.z, y);
            y = fmaf(z[c][3], wa.w, y);
            y = fmaf(z[c][4], wb.x, y);
            y = fmaf(z[c][5], wb.y, y);
            y = fmaf(z[c][6], wb.z, y);
            y = fmaf(z[c][7], wb.w, y);
            y = fmaf(z[c][8], wc.x, y);
            y = fmaf(z[c][9], wc.y, y);
            upd[c] = fmaf(fmaxf(y, 0.f), w3k, upd[c]);
        }
    }
#pragma unroll
    for (int c = 0; c < 4; c++) {
        int j = c * 256 + tid;
        g_NW[i * N_U + j] = w[c] + upd[c];
    }
}

// ---------------------------------------------------------------------------
// Transpose + fp16 split NW -> g_Bhi/g_Blo [n][k]
// ---------------------------------------------------------------------------
__global__ void __launch_bounds__(256) transpose_split_kernel() {
    __shared__ float tile[32][33];
    int bx = blockIdx.x, by = blockIdx.y;
    int tx = threadIdx.x, ty = threadIdx.y;           // 32 x 8
    int i0 = by * 32, j0 = bx * 32;
#pragma unroll
    for (int r = 0; r < 4; r++)
        tile[ty * 4 + r][tx] = g_NW[(i0 + ty * 4 + r) * N_U + j0 + tx];
    __syncthreads();
#pragma unroll
    for (int r = 0; r < 4; r++) {
        int j = j0 + ty * 4 + r;
        int i = i0 + tx;
        float v  = tile[tx][ty * 4 + r];
        __half h = __float2half_rn(v);
        __half l = __float2half_rn(v - __half2float(h));
        g_Bhi[j * N_U + i] = __half_as_ushort(h);
        g_Blo[j * N_U + i] = __half_as_ushort(l);
    }
}

// ---------------------------------------------------------------------------
// GEMM: out = relu( Ahi*Bhi + Ahi*Blo + Alo*Bhi ), fp16 mma.sync f32-acc.
// BM=112, BN=256 -> grid 37x4 = 148 CTAs (one balanced wave).
// 256 threads, 8 warps: each warp covers 112 rows x 32 cols (7x4 frags).
// M padded: A loads clamp row, stores guarded. 4-stage cp.async, 80B rows.
// ---------------------------------------------------------------------------
#define BM 112
#define BN 256
#define BK 32
#define STAGES 4
#define AROW 40
#define ABYTES (BM * AROW * 2)           // 8960
#define BBYTES (BN * AROW * 2)           // 20480
#define STBYTES (ABYTES + BBYTES)        // 29440
#define SMEM_GEMM (STAGES * STBYTES)     // 117760

__global__ void __launch_bounds__(256, 1) gemm_mma_kernel(float* __restrict__ out) {
    extern __shared__ char smem[];
    uint32_t sb = smem_u32(smem);
    int tid  = threadIdx.x;
    int wid  = tid >> 5;
    int lane = tid & 31;

    int mt = blockIdx.x % 37;
    int nt = blockIdx.x / 37;
    int nw = wid;

    const unsigned short* Aseg[3];
    const unsigned short* Bseg[3];
    Aseg[0] = g_Ahi;  Aseg[1] = g_Ahi;  Aseg[2] = g_Alo;
    Bseg[0] = g_Bhi + (size_t)(nt * BN) * N_U;
    Bseg[1] = g_Blo + (size_t)(nt * BN) * N_U;
    Bseg[2] = Bseg[0];

    float c[7][4][4];
#pragma unroll
    for (int f = 0; f < 7; f++)
#pragma unroll
        for (int n = 0; n < 4; n++)
#pragma unroll
            for (int q = 0; q < 4; q++) c[f][n][q] = 0.f;

    const int ITERS = 96;

    auto load_stage = [&](int it, int st) {
        int seg = it >> 5;
        int k0  = (it & 31) * BK;
        uint32_t abase = sb + st * STBYTES;
        uint32_t bbase = abase + ABYTES;
        const unsigned short* Ag = Aseg[seg];
        const unsigned short* Bg = Bseg[seg];
#pragma unroll
        for (int q = 0; q < 2; q++) {
            int chunk = tid + q * 256;
            if (chunk < BM * 4) {
                int row = chunk >> 2;
                int off = (chunk & 3) * 8;
                int grow = mt * BM + row;
                if (grow > 4095) grow = 4095;
                CP_ASYNC16(abase + row * (AROW * 2) + off * 2,
                           (const char*)(Ag + (size_t)grow * N_U + k0 + off));
            }
        }
#pragma unroll
        for (int q = 0; q < 4; q++) {
            int chunk = tid + q * 256;
            int row = chunk >> 2;
            int off = (chunk & 3) * 8;
            CP_ASYNC16(bbase + row * (AROW * 2) + off * 2,
                       (const char*)(Bg + (size_t)row * N_U + k0 + off));
        }
    };

#pragma unroll
    for (int s = 0; s < STAGES - 1; s++) {
        load_stage(s, s);
        CP_COMMIT();
    }

    int lrow = lane & 15;
    int lcol = (lane >> 4) * 16;

    for (int i = 0; i < ITERS; i++) {
        CP_WAIT(2);
        __syncthreads();

        int nx = i + STAGES - 1;
        if (nx < ITERS) load_stage(nx, nx & (STAGES - 1));
        CP_COMMIT();

        int st = i & (STAGES - 1);
        uint32_t abase = sb + st * STBYTES;
        uint32_t bbase = abase + ABYTES;

#pragma unroll
        for (int ks = 0; ks < 2; ks++) {
            uint32_t a[7][4];
#pragma unroll
            for (int f = 0; f < 7; f++)
                LDMATRIX_X4(a[f][0], a[f][1], a[f][2], a[f][3],
                    abase + (f * 16 + lrow) * (AROW * 2) + ks * 32 + lcol);
            uint32_t b[4][2];
#pragma unroll
            for (int g = 0; g < 2; g++) {
                uint32_t r0, r1, r2, r3;
                LDMATRIX_X4(r0, r1, r2, r3,
                    bbase + (nw * 32 + g * 16 + lrow) * (AROW * 2) + ks * 32 + lcol);
                b[2 * g][0] = r0;  b[2 * g][1] = r2;
                b[2 * g + 1][0] = r1;  b[2 * g + 1][1] = r3;
            }
#pragma unroll
            for (int f = 0; f < 7; f++)
#pragma unroll
                for (int n = 0; n < 4; n++)
                    MMA_F16F32(c[f][n][0], c[f][n][1], c[f][n][2], c[f][n][3],
                               a[f][0], a[f][1], a[f][2], a[f][3], b[n][0], b[n][1]);
        }
    }

    // Epilogue: relu + guarded store
    int cbase = nt * BN + nw * 32 + (lane & 3) * 2;
#pragma unroll
    for (int f = 0; f < 7; f++) {
        int r = mt * BM + f * 16 + (lane >> 2);
#pragma unroll
        for (int n = 0; n < 4; n++) {
            int cc = cbase + n * 8;
            if (r < BATCH) {
                float2 v0;
                v0.x = fmaxf(c[f][n][0], 0.f);
                v0.y = fmaxf(c[f][n][1], 0.f);
                *(float2*)(out + (size_t)r * N_U + cc) = v0;
            }
            if (r + 8 < BATCH) {
                float2 v1;
                v1.x = fmaxf(c[f][n][2], 0.f);
                v1.y = fmaxf(c[f][n][3], 0.f);
                *(float2*)(out + (size_t)(r + 8) * N_U + cc) = v1;
            }
        }
    }
}

// ---------------------------------------------------------------------------
// Row softmax in-place
// ---------------------------------------------------------------------------
__global__ void __launch_bounds__(256) softmax_kernel(float* __restrict__ out) {
    __shared__ float redm[8];
    __shared__ float reds[8];
    __shared__ float bval[2];
    int row = blockIdx.x, tid = threadIdx.x;
    int lane = tid & 31, wid = tid >> 5;

    float4 v = *(float4*)(out + row * N_U + tid * 4);
    float m = fmaxf(fmaxf(v.x, v.y), fmaxf(v.z, v.w));
#pragma unroll
    for (int o = 16; o > 0; o >>= 1) m = fmaxf(m, __shfl_xor_sync(0xffffffffu, m, o));
    if (lane == 0) redm[wid] = m;
    __syncthreads();
    if (tid == 0) {
        float t = redm[0];
#pragma unroll
        for (int i = 1; i < 8; i++) t = fmaxf(t, redm[i]);
        bval[0] = t;
    }
    __syncthreads();
    m = bval[0];
    v.x = __expf(v.x - m); v.y = __expf(v.y - m);
    v.z = __expf(v.z - m); v.w = __expf(v.w - m);
    float s = v.x + v.y + v.z + v.w;
#pragma unroll
    for (int o = 16; o > 0; o >>= 1) s += __shfl_xor_sync(0xffffffffu, s, o);
    if (lane == 0) reds[wid] = s;
    __syncthreads();
    if (tid == 0) {
        float t = 0.f;
#pragma unroll
        for (int i = 0; i < 8; i++) t += reds[i];
        bval[1] = 1.f / t;
    }
    __syncthreads();
    float inv = bval[1];
    v.x *= inv; v.y *= inv; v.z *= inv; v.w *= inv;
    *(float4*)(out + row * N_U + tid * 4) = v;
}

// ---------------------------------------------------------------------------
// Entry point
// ---------------------------------------------------------------------------
extern "C" void kernel_launch(void* const* d_in, const int* in_sizes, int n_in,
                              void* d_out, int out_size) {
    const float* X      = (const float*)d_in[0];
    const float* weight = (const float*)d_in[1];
    const float* W1     = (const float*)d_in[3];
    const float* b1     = (const float*)d_in[4];
    const float* W2     = (const float*)d_in[5];
    const float* b2     = (const float*)d_in[6];
    const float* W3     = (const float*)d_in[7];
    const float* b3     = (const float*)d_in[8];
    float* out = (float*)d_out;

    static bool attr_done = false;
    if (!attr_done) {
        cudaFuncSetAttribute(gemm_mma_kernel,
                             cudaFuncAttributeMaxDynamicSharedMemorySize, SMEM_GEMM);
        attr_done = true;
    }

    prep_kernel<<<5329, 256>>>(X, weight, W1, b1);                      // 1
    fold_kernel<<<8, 256>>>();                                          // 2
    mlp_kernel<<<N_U, 256>>>(weight, W2, b2, W3, b3);                   // 3
    transpose_split_kernel<<<dim3(32, 32), dim3(32, 8)>>>();            // 4
    gemm_mma_kernel<<<148, 256, SMEM_GEMM>>>(out);                      // 5
    softmax_kernel<<<BATCH, 256>>>(out);                                // 6
}